// round 16
// baseline (speedup 1.0000x reference)
#include <cuda_runtime.h>
#include <cstdint>
#include <cmath>

// Problem dims: B=32, S=513 (T=512 ctx + 1 query), D=1024, K=256, V=256, H=2048, O=256
#define PB 32
#define PT 512
#define PD 1024
#define PK 256
#define PV 256
#define PH 2048
#define PO 256

// ---------------- device scratch ----------------
__device__ float g_xKh[(size_t)PB * PT * PK];           // 16 MB tf32-hi
__device__ float g_xKl[(size_t)PB * PT * PK];           // 16 MB tf32-lo
__device__ float g_xQ[PB * PK];
__device__ float g_L0[(size_t)PB * PT * PH];            // 128 MB
__device__ float g_G [(size_t)PB * PT * PT];            // 32 MB (lower triangle valid)
__device__ float g_q0[PB * PH];
__device__ float g_qk[PB * PT];
__device__ float g_wt[PB * PH];
__device__ float g_wv[PB * PT];
__device__ float g_ybar[PB * PD];
__device__ float g_mhn[PB * PV];
__device__ float g_rpart[4 * PB * PD];                  // reinst h-split partials
__device__ unsigned g_done4[PB * 4];                    // per-(batch,rowblock) gemm counters
__device__ unsigned g_sdone[PB];                        // per-batch scan-complete flags

__constant__ unsigned c_rbneed[4] = {17u, 18u, 19u, 20u};  // tiles per rowblock

// ================= mma.sync tf32 helpers (NOT arch-variant-gated) =================
__device__ __forceinline__ uint32_t smem_u32(const void* p) {
    uint32_t a;
    asm("{ .reg .u64 t; cvta.to.shared.u64 t, %1; cvt.u32.u64 %0, t; }" : "=r"(a) : "l"(p));
    return a;
}
__device__ __forceinline__ uint32_t tf32_hi(uint32_t raw) {
    uint32_t u;
    asm("cvt.rna.tf32.f32 %0, %1;" : "=r"(u) : "f"(__uint_as_float(raw)));
    return u;
}
__device__ __forceinline__ uint32_t tf32_lo(uint32_t raw, uint32_t hi) {
    float d = __uint_as_float(raw) - __uint_as_float(hi);
    uint32_t u;
    asm("cvt.rna.tf32.f32 %0, %1;" : "=r"(u) : "f"(d));
    return u;
}
__device__ __forceinline__ void ldmx4(uint32_t* r, uint32_t addr) {
    asm volatile("ldmatrix.sync.aligned.m8n8.x4.shared.b16 {%0,%1,%2,%3}, [%4];"
                 : "=r"(r[0]), "=r"(r[1]), "=r"(r[2]), "=r"(r[3]) : "r"(addr));
}
__device__ __forceinline__ void ldmx2(uint32_t* r, uint32_t addr) {
    asm volatile("ldmatrix.sync.aligned.m8n8.x2.shared.b16 {%0,%1}, [%2];"
                 : "=r"(r[0]), "=r"(r[1]) : "r"(addr));
}
__device__ __forceinline__ void mma8(float* c, const uint32_t* a, const uint32_t* b) {
    asm volatile(
        "mma.sync.aligned.m16n8k8.row.col.f32.tf32.tf32.f32 "
        "{%0,%1,%2,%3}, {%4,%5,%6,%7}, {%8,%9}, {%0,%1,%2,%3};"
        : "+f"(c[0]), "+f"(c[1]), "+f"(c[2]), "+f"(c[3])
        : "r"(a[0]), "r"(a[1]), "r"(a[2]), "r"(a[3]), "r"(b[0]), "r"(b[1]));
}
__device__ __forceinline__ void cp16(uint32_t dst, const void* src) {
    asm volatile("cp.async.ca.shared.global [%0], [%1], 16;" :: "r"(dst), "l"(src) : "memory");
}
__device__ __forceinline__ void cp_commit() {
    asm volatile("cp.async.commit_group;" ::: "memory");
}
__device__ __forceinline__ void cp_wait3() {
    asm volatile("cp.async.wait_group 3;" ::: "memory");
}
__device__ __forceinline__ void cp_wait1() {
    asm volatile("cp.async.wait_group 1;" ::: "memory");
}
__device__ __forceinline__ void cp_wait0() {
    asm volatile("cp.async.wait_group 0;" ::: "memory");
}

#define TSTRIDE 20                     // floats per smem row (16 data + 4 pad)
#define TILE_F (128 * TSTRIDE)
#define FUSED_SMEM (8 * TILE_F * 4)    // 81920 B
#define N_GEMM (74 * PB)               // 2368 gemm tiles
#define N_TAIL 640                     // 128 ybar + 512 reinst-partial blocks

// ================= GEMM 1: xK projection (128x128 tiles, fp32 in, cvt in-register) =================
__global__ void __launch_bounds__(256) gemm_mma(
    const float* __restrict__ Ag, const float* __restrict__ Bg,
    float* __restrict__ Ch, float* __restrict__ Cl,
    int N, int Kd)
{
    __shared__ __align__(16) float smA[2][TILE_F];
    __shared__ __align__(16) float smB[2][TILE_F];

    const float* A = Ag;
    const float* B = Bg;
    const int m0 = blockIdx.y * 128;
    const int n0 = blockIdx.x * 128;
    const int tid = threadIdx.x, wid = tid >> 5, lane = tid & 31;
    const int wm = (wid & 1) * 64;
    const int wn = (wid >> 1) * 32;

    float acc[4][4][4];
    #pragma unroll
    for (int i = 0; i < 4; i++)
        #pragma unroll
        for (int j = 0; j < 4; j++)
            #pragma unroll
            for (int k = 0; k < 4; k++) acc[i][j][k] = 0.f;

    const int p_row0 = tid >> 2, p_q0 = tid & 3;
    const int p_row1 = (tid + 256) >> 2;

    const uint32_t sa0 = smem_u32(smA[0]);
    const uint32_t sb0 = smem_u32(smB[0]);

    const int a_r = (lane & 7) + ((lane >> 3) & 1) * 8;
    const int a_c = (lane >> 4) * 4;
    const int b_r = (lane & 7);
    const int b_c = ((lane >> 3) & 1) * 4;
    const uint32_t aOff = (uint32_t)(((wm + a_r) * TSTRIDE + a_c) * 4);
    const uint32_t bOff = (uint32_t)(((wn + b_r) * TSTRIDE + b_c) * 4);

    const int nc = Kd >> 4;

    auto issue = [&](int c, int bu) {
        const int k0 = c * 16;
        {
            long am = (long)(m0 + p_row0);
            long ar = am + (am >> 9);          // skip query rows
            cp16(sa0 + (uint32_t)((bu * TILE_F + p_row0 * TSTRIDE + p_q0 * 4) * 4),
                 A + ar * (long)Kd + k0 + p_q0 * 4);
            cp16(sb0 + (uint32_t)((bu * TILE_F + p_row0 * TSTRIDE + p_q0 * 4) * 4),
                 B + (long)(n0 + p_row0) * Kd + k0 + p_q0 * 4);
        }
        {
            long am = (long)(m0 + p_row1);
            long ar = am + (am >> 9);
            cp16(sa0 + (uint32_t)((bu * TILE_F + p_row1 * TSTRIDE + p_q0 * 4) * 4),
                 A + ar * (long)Kd + k0 + p_q0 * 4);
            cp16(sb0 + (uint32_t)((bu * TILE_F + p_row1 * TSTRIDE + p_q0 * 4) * 4),
                 B + (long)(n0 + p_row1) * Kd + k0 + p_q0 * 4);
        }
        cp_commit();
    };

    issue(0, 0);
    for (int c = 0; c < nc; c++) {
        const int bu = c & 1;
        if (c + 1 < nc) { issue(c + 1, bu ^ 1); cp_wait1(); }
        else            { cp_wait0(); }
        __syncthreads();

        const uint32_t aB = sa0 + (uint32_t)(bu * TILE_F * 4) + aOff;
        const uint32_t bB = sb0 + (uint32_t)(bu * TILE_F * 4) + bOff;

        #pragma unroll
        for (int k8 = 0; k8 < 2; k8++) {
            uint32_t ar[4][4], br[4][2];
            #pragma unroll
            for (int mi = 0; mi < 4; mi++)
                ldmx4(ar[mi], aB + (uint32_t)((mi * 16 * TSTRIDE) * 4 + k8 * 32));
            #pragma unroll
            for (int ni = 0; ni < 4; ni++)
                ldmx2(br[ni], bB + (uint32_t)((ni * 8 * TSTRIDE) * 4 + k8 * 32));

            uint32_t ah[4][4], bh[4][2];
            #pragma unroll
            for (int mi = 0; mi < 4; mi++)
                #pragma unroll
                for (int j = 0; j < 4; j++) ah[mi][j] = tf32_hi(ar[mi][j]);
            #pragma unroll
            for (int ni = 0; ni < 4; ni++)
                #pragma unroll
                for (int j = 0; j < 2; j++) bh[ni][j] = tf32_hi(br[ni][j]);

            #pragma unroll
            for (int mi = 0; mi < 4; mi++)
                #pragma unroll
                for (int ni = 0; ni < 4; ni++) mma8(acc[mi][ni], ah[mi], bh[ni]);

            uint32_t bl[4][2];
            #pragma unroll
            for (int ni = 0; ni < 4; ni++)
                #pragma unroll
                for (int j = 0; j < 2; j++) bl[ni][j] = tf32_lo(br[ni][j], bh[ni][j]);
            #pragma unroll
            for (int mi = 0; mi < 4; mi++)
                #pragma unroll
                for (int ni = 0; ni < 4; ni++) mma8(acc[mi][ni], ah[mi], bl[ni]);

            uint32_t al[4][4];
            #pragma unroll
            for (int mi = 0; mi < 4; mi++)
                #pragma unroll
                for (int j = 0; j < 4; j++) al[mi][j] = tf32_lo(ar[mi][j], ah[mi][j]);
            #pragma unroll
            for (int mi = 0; mi < 4; mi++)
                #pragma unroll
                for (int ni = 0; ni < 4; ni++) mma8(acc[mi][ni], al[mi], bh[ni]);
        }
        __syncthreads();
    }

    const int er = lane >> 2, ec = (lane & 3) * 2;
    #pragma unroll
    for (int mi = 0; mi < 4; mi++) {
        long row = m0 + wm + mi * 16 + er;
        #pragma unroll
        for (int ni = 0; ni < 4; ni++) {
            long col = n0 + wn + ni * 8 + ec;
            #pragma unroll
            for (int half = 0; half < 2; half++) {
                long off = (row + half * 8) * (long)N + col;
                float v0 = acc[mi][ni][half * 2 + 0];
                float v1 = acc[mi][ni][half * 2 + 1];
                uint32_t h0 = tf32_hi(__float_as_uint(v0));
                uint32_t h1 = tf32_hi(__float_as_uint(v1));
                *reinterpret_cast<float2*>(Ch + off) =
                    make_float2(__uint_as_float(h0), __uint_as_float(h1));
                *reinterpret_cast<float2*>(Cl + off) =
                    make_float2(__uint_as_float(tf32_lo(__float_as_uint(v0), h0)),
                                __uint_as_float(tf32_lo(__float_as_uint(v1), h1)));
            }
        }
    }
}

// ---------------- xQ = x[b, 512, :] @ W_Q^T ; also resets handshake counters ----------------
__global__ void xq_kernel(const float* __restrict__ x, const float* __restrict__ WQ,
                          float* __restrict__ out_xq)
{
    if (blockIdx.x == 0 && blockIdx.y == 0) {
        if (threadIdx.x < PB * 4) g_done4[threadIdx.x] = 0u;
        if (threadIdx.x < PB)     g_sdone[threadIdx.x] = 0u;
    }

    int b = blockIdx.x;
    int w = threadIdx.x >> 5, lane = threadIdx.x & 31;
    int n = blockIdx.y * 8 + w;
    const float* xr = x + ((long)b * 513 + 512) * PD;
    const float* wr = WQ + (long)n * PD;
    float s = 0.f;
    for (int k = lane * 4; k < PD; k += 128) {
        float4 a = *reinterpret_cast<const float4*>(xr + k);
        float4 c = *reinterpret_cast<const float4*>(wr + k);
        s += a.x * c.x + a.y * c.y + a.z * c.z + a.w * c.w;
    }
    #pragma unroll
    for (int o = 16; o; o >>= 1) s += __shfl_down_sync(0xffffffffu, s, o);
    if (!lane) {
        g_xQ[b * PK + n] = s;
        out_xq[b * PK + n] = s;
    }
}

// ---------------- merged dots: q0[b,h]=W_hi0[b,h]·xQ ; qk[b,t]=(xKh+xKl)[b,t]·xQ ----------------
__global__ void __launch_bounds__(256) dots_kernel(const float* __restrict__ Whi0)
{
    int b = blockIdx.x, y = blockIdx.y;
    int w = threadIdx.x >> 5, lane = threadIdx.x & 31;
    const float* q = g_xQ + b * PK;
    if (y < PH / 8) {
        int r = y * 8 + w;
        const float* row = Whi0 + ((long)b * PH + r) * PK;
        float s = 0.f;
        for (int k = lane * 4; k < PK; k += 128) {
            float4 a = *reinterpret_cast<const float4*>(row + k);
            float4 qq = *reinterpret_cast<const float4*>(q + k);
            s += a.x * qq.x + a.y * qq.y + a.z * qq.z + a.w * qq.w;
        }
        #pragma unroll
        for (int o = 16; o; o >>= 1) s += __shfl_down_sync(0xffffffffu, s, o);
        if (!lane) g_q0[b * PH + r] = s;
    } else {
        int r = (y - PH / 8) * 8 + w;
        const float* rh = g_xKh + ((size_t)b * PT + r) * PK;
        const float* rl = g_xKl + ((size_t)b * PT + r) * PK;
        float s = 0.f;
        for (int k = lane * 4; k < PK; k += 128) {
            float4 ah = *reinterpret_cast<const float4*>(rh + k);
            float4 al = *reinterpret_cast<const float4*>(rl + k);
            float4 qq = *reinterpret_cast<const float4*>(q + k);
            s += (ah.x + al.x) * qq.x + (ah.y + al.y) * qq.y
               + (ah.z + al.z) * qq.z + (ah.w + al.w) * qq.w;
        }
        #pragma unroll
        for (int o = 16; o; o >>= 1) s += __shfl_down_sync(0xffffffffu, s, o);
        if (!lane) g_qk[b * PT + r] = s;
    }
}

// ================= FUSED: gemm (L0 + tri G, rowblock-ordered) + pipelined scan + tail1 =================
// blocks [0,PB): scan role — gates per 128-row block on g_done4[b][rb], so it
//   pipelines BEHIND the gemm wave instead of waiting for all 74 tiles.
// blocks [PB, PB+N_GEMM): gemm role, batch-major, rowblock-ascending within batch.
// blocks [PB+N_GEMM, ...): tail1 role (ybar + reinst partials), waits g_sdone[b].
__global__ void __launch_bounds__(256, 2) lg_scan_kernel(
    const float* __restrict__ xKh, const float* __restrict__ xKl,
    const float* __restrict__ Whi0,
    float* __restrict__ L0g, float* __restrict__ Gg,
    const float* __restrict__ x, const float* __restrict__ W_reinst0)
{
    extern __shared__ float sm[];
    const int tid = threadIdx.x;

    if (blockIdx.x < PB) {
        // ======== SCAN ROLE ========
        const int b = blockIdx.x;
        __shared__ unsigned redm[2][8];
        __shared__ unsigned redh[2][8];
        __shared__ float redf[8];

        const float* L0b = g_L0 + (size_t)b * PT * PH;
        const float* Gb  = g_G  + (size_t)b * PT * PT;
        const uint32_t sB = smem_u32(sm);
        const uint32_t sGo = (uint32_t)(5 * PH * 4);
        float* L0s = sm;
        float* Gs  = sm + 5 * PH;

        auto wait_rb = [&](int rb) {
            if (tid == 0) {
                unsigned need = c_rbneed[rb];
                while (atomicAdd(&g_done4[b * 4 + rb], 0u) < need) __nanosleep(128);
                __threadfence();
            }
            __syncthreads();
        };

        int last[8];
        #pragma unroll
        for (int i = 0; i < 8; i++) last[i] = -1;

        auto issue_row = [&](int r) {
            const int sl = r % 5;
            cp16(sB + (uint32_t)((sl * PH + tid * 4) * 4),         L0b + (size_t)r * PH + tid * 4);
            cp16(sB + (uint32_t)((sl * PH + (tid + 256) * 4) * 4), L0b + (size_t)r * PH + (tid + 256) * 4);
            if (tid < 128)
                cp16(sB + sGo + (uint32_t)((sl * PT + tid * 4) * 4), Gb + (size_t)r * PT + tid * 4);
        };

        wait_rb(0);
        #pragma unroll
        for (int r = 0; r < 4; r++) { issue_row(r); cp_commit(); }
        cp_wait3();
        __syncthreads();

        const int lane = tid & 31, w = tid >> 5;
        int slot = 0;

        for (int t = 0; t < PT; t++) {
            const float* gr = Gs + slot * PT;
            const float* lr = L0s + slot * PH;

            unsigned bestm;
            int besth;
            {
                float v = last[0] < 0 ? lr[tid] : gr[last[0]];
                unsigned u = __float_as_uint(v);
                bestm = (u & 0x80000000u) ? ~u : (u | 0x80000000u);
                besth = tid;
            }
            #pragma unroll
            for (int i = 1; i < 8; i++) {
                float v = last[i] < 0 ? lr[i * 256 + tid] : gr[last[i]];
                unsigned u = __float_as_uint(v);
                u = (u & 0x80000000u) ? ~u : (u | 0x80000000u);
                if (u > bestm) { bestm = u; besth = i * 256 + tid; }
            }
            unsigned m1 = __reduce_max_sync(0xffffffffu, bestm);
            unsigned hc = (bestm == m1) ? (unsigned)besth : 0xffffffffu;
            unsigned mh = __reduce_min_sync(0xffffffffu, hc);
            if (lane == 0) { redm[t & 1][w] = m1; redh[t & 1][w] = mh; }

            if (t + 4 < PT) {
                const int r = t + 4;
                if ((r & 127) == 0) wait_rb(r >> 7);   // gate on next rowblock's tiles
                issue_row(r);
            }
            cp_commit();
            cp_wait3();
            __syncthreads();

            unsigned bm = redm[t & 1][0], bh = redh[t & 1][0];
            #pragma unroll
            for (int j = 1; j < 8; j++) {
                unsigned m2 = redm[t & 1][j], h2 = redh[t & 1][j];
                if (m2 > bm || (m2 == bm && h2 < bh)) { bm = m2; bh = h2; }
            }
            if ((int)(bh & 255u) == tid) last[bh >> 8] = t;

            slot = (slot == 4) ? 0 : slot + 1;
        }

        // ---- inline softmax + weight split ----
        g_wv[b * PT + tid]       = 0.f;
        g_wv[b * PT + 256 + tid] = 0.f;

        float l[8];
        float mx = -3.4e38f;
        #pragma unroll
        for (int i = 0; i < 8; i++) {
            int h = i * 256 + tid;
            int t = last[i];
            l[i] = (t < 0) ? g_q0[b * PH + h] : g_qk[b * PT + t];
            mx = fmaxf(mx, l[i]);
        }
        #pragma unroll
        for (int o = 16; o; o >>= 1) mx = fmaxf(mx, __shfl_xor_sync(0xffffffffu, mx, o));
        if (!lane) redf[w] = mx;
        __syncthreads();
        mx = redf[0];
        #pragma unroll
        for (int j = 1; j < 8; j++) mx = fmaxf(mx, redf[j]);

        float s = 0.f;
        #pragma unroll
        for (int i = 0; i < 8; i++) { l[i] = expf(l[i] - mx); s += l[i]; }
        #pragma unroll
        for (int o = 16; o; o >>= 1) s += __shfl_xor_sync(0xffffffffu, s, o);
        __syncthreads();
        if (!lane) redf[w] = s;
        __syncthreads();
        s = 0.f;
        #pragma unroll
        for (int j = 0; j < 8; j++) s += redf[j];

        float inv = 1.f / s;
        #pragma unroll
        for (int i = 0; i < 8; i++) {
            int h = i * 256 + tid;
            float wgt = l[i] * inv;
            if (last[i] < 0) {
                g_wt[b * PH + h] = wgt;
            } else {
                g_wt[b * PH + h] = 0.f;
                g_wv[b * PT + last[i]] = wgt;
            }
        }

        __threadfence();
        __syncthreads();
        if (tid == 0) atomicAdd(&g_sdone[b], 1u);
        return;
    }

    if (blockIdx.x >= PB + N_GEMM) {
        // ======== TAIL1 ROLE (ybar + reinst partials) ========
        const int i = blockIdx.x - (PB + N_GEMM);
        float* sb = sm;
        if (i < 128) {
            int b = i >> 2, d0 = (i & 3) * 256;
            if (tid == 0) {
                while (atomicAdd(&g_sdone[b], 0u) == 0u) __nanosleep(256);
                __threadfence();
            }
            __syncthreads();
            sb[tid]       = g_wv[b * PT + tid];
            sb[256 + tid] = g_wv[b * PT + 256 + tid];
            __syncthreads();
            float yb = 0.f;
            const float* xb = x + (size_t)b * 513 * PD + d0 + tid;
            #pragma unroll 16
            for (int t = 0; t < PT; t++) yb += sb[t] * xb[(size_t)t * PD];
            g_ybar[b * PD + d0 + tid] = yb;
        } else {
            int j = i - 128;
            int z = j >> 7, low = j & 127;
            int b = low >> 2, d0 = (low & 3) * 256;
            if (tid == 0) {
                while (atomicAdd(&g_sdone[b], 0u) == 0u) __nanosleep(256);
                __threadfence();
            }
            __syncthreads();
            sb[tid]       = g_wt[b * PH + z * 512 + tid];
            sb[256 + tid] = g_wt[b * PH + z * 512 + 256 + tid];
            __syncthreads();
            float acc = 0.f;
            const float* Wb = W_reinst0 + (size_t)b * PH * PD + (size_t)(z * 512) * PD + d0 + tid;
            #pragma unroll 16
            for (int h = 0; h < 512; h++) acc += sb[h] * Wb[(size_t)h * PD];
            g_rpart[((size_t)z * PB + b) * PD + d0 + tid] = acc;
        }
        return;
    }

    // ======== GEMM ROLE (rowblock-ascending within batch) ========
    const int idx = blockIdx.x - PB;
    const int z = idx / 74;
    const int tile = idx % 74;

    int rb, local;
    if      (tile < 17) { rb = 0; local = tile; }
    else if (tile < 35) { rb = 1; local = tile - 17; }
    else if (tile < 54) { rb = 2; local = tile - 35; }
    else                { rb = 3; local = tile - 54; }

    const float* Ah = xKh + (long)z * PT * PK;
    const float* Al = xKl + (long)z * PT * PK;
    const float* Bh;
    const float* Bl = nullptr;
    float* C;
    int m0, n0, N;
    bool bs;
    if (local < 16) {                 // L0 tile
        bs = false;
        m0 = rb * 128;
        n0 = local * 128;
        N = PH;
        Bh = Whi0 + (long)z * PH * PK;
        C = L0g + (size_t)z * PT * PH;
    } else {                          // G tile (by=rb, bx=local-16 <= rb)
        bs = true;
        m0 = rb * 128;
        n0 = (local - 16) * 128;
        N = PT;
        Bh = xKh + (long)z * PT * PK;
        Bl = xKl + (long)z * PT * PK;
        C = Gg + (size_t)z * PT * PT;
    }
    const int Kd = PK;

    const int wid = tid >> 5, lane = tid & 31;
    const int wm = (wid & 1) * 64;
    const int wn = (wid >> 1) * 32;

    const uint32_t sbase = smem_u32(sm);
    const uint32_t OAH = 0, OAL = 2 * TILE_F, OBH = 4 * TILE_F, OBL = 6 * TILE_F;

    float acc[4][4][4];
    #pragma unroll
    for (int i = 0; i < 4; i++)
        #pragma unroll
        for (int j = 0; j < 4; j++)
            #pragma unroll
            for (int k = 0; k < 4; k++) acc[i][j][k] = 0.f;

    const int p_row0 = tid >> 2, p_q0 = tid & 3;
    const int p_row1 = (tid + 256) >> 2;

    const int a_r = (lane & 7) + ((lane >> 3) & 1) * 8;
    const int a_c = (lane >> 4) * 4;
    const int b_r = (lane & 7);
    const int b_c = ((lane >> 3) & 1) * 4;
    const uint32_t aOff = (uint32_t)(((wm + a_r) * TSTRIDE + a_c) * 4);
    const uint32_t bOff = (uint32_t)(((wn + b_r) * TSTRIDE + b_c) * 4);

    const int nc = Kd >> 4;

    auto issue = [&](int c, int bu) {
        const int k0 = c * 16;
        #pragma unroll
        for (int h = 0; h < 2; h++) {
            const int pr = h ? p_row1 : p_row0;
            const uint32_t dof = (uint32_t)((bu * TILE_F + pr * TSTRIDE + p_q0 * 4) * 4);
            const long aoff = (long)(m0 + pr) * Kd + k0 + p_q0 * 4;
            const long boff = (long)(n0 + pr) * Kd + k0 + p_q0 * 4;
            cp16(sbase + OAH * 4 + dof, Ah + aoff);
            cp16(sbase + OAL * 4 + dof, Al + aoff);
            cp16(sbase + OBH * 4 + dof, Bh + boff);
            if (bs) cp16(sbase + OBL * 4 + dof, Bl + boff);
        }
        cp_commit();
    };

    issue(0, 0);
    for (int c = 0; c < nc; c++) {
        const int bu = c & 1;
        if (c + 1 < nc) { issue(c + 1, bu ^ 1); cp_wait1(); }
        else            { cp_wait0(); }
        __syncthreads();

        const uint32_t bufo = (uint32_t)(bu * TILE_F * 4);
        const uint32_t aH = sbase + OAH * 4 + bufo + aOff;
        const uint32_t aL = sbase + OAL * 4 + bufo + aOff;
        const uint32_t bH = sbase + OBH * 4 + bufo + bOff;
        const uint32_t bL = sbase + OBL * 4 + bufo + bOff;

        #pragma unroll
        for (int k8 = 0; k8 < 2; k8++) {
            uint32_t ah[4][4], al[4][4], bh[4][2], bl[4][2];
            #pragma unroll
            for (int mi = 0; mi < 4; mi++) {
                const uint32_t o = (uint32_t)((mi * 16 * TSTRIDE) * 4 + k8 * 32);
                ldmx4(ah[mi], aH + o);
                ldmx4(al[mi], aL + o);
            }
            if (bs) {
                #pragma unroll
                for (int ni = 0; ni < 4; ni++) {
                    const uint32_t o = (uint32_t)((ni * 8 * TSTRIDE) * 4 + k8 * 32);
                    ldmx2(bh[ni], bH + o);
                    ldmx2(bl[ni], bL + o);
                }
            } else {
                #pragma unroll
                for (int ni = 0; ni < 4; ni++) {
                    uint32_t br[2];
                    ldmx2(br, bH + (uint32_t)((ni * 8 * TSTRIDE) * 4 + k8 * 32));
                    bh[ni][0] = tf32_hi(br[0]);
                    bh[ni][1] = tf32_hi(br[1]);
                    bl[ni][0] = tf32_lo(br[0], bh[ni][0]);
                    bl[ni][1] = tf32_lo(br[1], bh[ni][1]);
                }
            }

            #pragma unroll
            for (int mi = 0; mi < 4; mi++)
                #pragma unroll
                for (int ni = 0; ni < 4; ni++) mma8(acc[mi][ni], ah[mi], bh[ni]);
            #pragma unroll
            for (int mi = 0; mi < 4; mi++)
                #pragma unroll
                for (int ni = 0; ni < 4; ni++) mma8(acc[mi][ni], ah[mi], bl[ni]);
            #pragma unroll
            for (int mi = 0; mi < 4; mi++)
                #pragma unroll
                for (int ni = 0; ni < 4; ni++) mma8(acc[mi][ni], al[mi], bh[ni]);
        }
        __syncthreads();
    }

    const int er = lane >> 2, ec = (lane & 3) * 2;
    #pragma unroll
    for (int mi = 0; mi < 4; mi++) {
        long row = m0 + wm + mi * 16 + er;
        #pragma unroll
        for (int ni = 0; ni < 4; ni++) {
            long col = n0 + wn + ni * 8 + ec;
            *reinterpret_cast<float2*>(C + row * (long)N + col) =
                make_float2(acc[mi][ni][0], acc[mi][ni][1]);
            *reinterpret_cast<float2*>(C + (row + 8) * (long)N + col) =
                make_float2(acc[mi][ni][2], acc[mi][ni][3]);
        }
    }

    __threadfence();
    __syncthreads();
    if (tid == 0) atomicAdd(&g_done4[z * 4 + rb], 1u);
}

// ---------------- tail2: reinst reduce (128 blocks) || mhn (256 blocks) ----------------
__global__ void __launch_bounds__(256) tail2_kernel(
    const float* __restrict__ W_oh0, const float* __restrict__ W_V,
    float* __restrict__ out_reinst)
{
    int i = blockIdx.x, tid = threadIdx.x;
    if (i < 128) {
        int b = i >> 2;
        int d = (i & 3) * 256 + tid;
        float s = g_ybar[b * PD + d];
        #pragma unroll
        for (int z = 0; z < 4; z++) s += g_rpart[((size_t)z * PB + b) * PD + d];
        out_reinst[b * PD + d] = s;
    } else {
        int k = i - 128;
        int b = k >> 3, v0 = (k & 7) * 32;
        int lane = tid & 31, w = tid >> 5;
        __shared__ float wt_s[PH];
        __shared__ float yb_s[PD];
        #pragma unroll
        for (int q = 0; q < 8; q++) wt_s[q * 256 + tid] = g_wt[b * PH + q * 256 + tid];
        #pragma unroll
        for (int q = 0; q < 4; q++) yb_s[q * 256 + tid] = g_ybar[b * PD + q * 256 + tid];
        __syncthreads();

        for (int pass = 0; pass < 4; pass++) {
            int v = v0 + pass * 8 + w;
            const float* row = W_oh0 + ((long)b * PV + v) * PH;
            float s = 0.f;
            #pragma unroll 4
            for (int h = lane * 4; h < PH; h += 128) {
                float4 a = *reinterpret_cast<const float4*>(row + h);
                s += a.x * wt_s[h] + a.y * wt_s[h + 1] + a.z * wt_s[h + 2] + a.w * wt_s[h + 3];
            }
            const float* wvr = W_V + (long)v * PD;
            #pragma unroll 4
            for (int d = lane * 4; d < PD; d += 128) {
                float4 a = *reinterpret_cast<const float4*>(wvr + d);
                s += a.x * yb_s[d] + a.y * yb_s[d + 1] + a.z * yb_s[d + 2] + a.w * yb_s[d + 3];
            }
            #pragma unroll
            for (int o = 16; o; o >>= 1) s += __shfl_down_sync(0xffffffffu, s, o);
            if (!lane) g_mhn[b * PV + v] = s;
        }
    }
}

// ---------------- out[b,o] = mhn[b,:]@W_proj[o,:]  (grid: B x 8) ----------------
__global__ void __launch_bounds__(256) proj_kernel(
    const float* __restrict__ W_proj, float* __restrict__ outp)
{
    int b = blockIdx.x, tid = threadIdx.x, lane = tid & 31, w = tid >> 5;
    int o0 = blockIdx.y * 32;
    __shared__ float mhn_s[PV];
    if (tid < PV) mhn_s[tid] = g_mhn[b * PV + tid];
    __syncthreads();

    for (int pass = 0; pass < 4; pass++) {
        int o = o0 + pass * 8 + w;
        const float* pr = W_proj + (long)o * PV;
        float s = 0.f;
        for (int vv = lane * 4; vv < PV; vv += 128) {
            float4 a = *reinterpret_cast<const float4*>(pr + vv);
            s += a.x * mhn_s[vv] + a.y * mhn_s[vv + 1] + a.z * mhn_s[vv + 2] + a.w * mhn_s[vv + 3];
        }
        #pragma unroll
        for (int oo = 16; oo; oo >>= 1) s += __shfl_down_sync(0xffffffffu, s, oo);
        if (!lane) outp[b * PO + o] = s;
    }
}

// ---------------- launch ----------------
extern "C" void kernel_launch(void* const* d_in, const int* in_sizes, int n_in,
                              void* d_out, int out_size)
{
    const float* x         = (const float*)d_in[0];
    const float* W_Q       = (const float*)d_in[1];
    const float* W_K       = (const float*)d_in[2];
    const float* W_V       = (const float*)d_in[3];
    const float* W_proj    = (const float*)d_in[4];
    const float* W_hi0     = (const float*)d_in[5];
    const float* W_oh0     = (const float*)d_in[6];
    const float* W_reinst0 = (const float*)d_in[7];
    float* out = (float*)d_out;

    float *pxKh, *pxKl, *pL0, *pG;
    cudaGetSymbolAddress((void**)&pxKh, g_xKh);
    cudaGetSymbolAddress((void**)&pxKl, g_xKl);
    cudaGetSymbolAddress((void**)&pL0,  g_L0);
    cudaGetSymbolAddress((void**)&pG,   g_G);

    cudaFuncSetAttribute((const void*)lg_scan_kernel,
                         cudaFuncAttributeMaxDynamicSharedMemorySize, FUSED_SMEM);

    // output layout: [out 32x256 | reinst 32x1024 | xQ 32x256]
    float* out_main   = out;
    float* out_reinst = out + PB * PO;
    float* out_xq     = out + PB * PO + PB * PD;

    // 1) xK = ctx @ W_K^T, stored as tf32 hi/lo pair
    gemm_mma<<<dim3(2, 128, 1), 256>>>(x, W_K, pxKh, pxKl, PK, PD);

    // 2) xQ (also resets handshake counters)
    xq_kernel<<<dim3(PB, PK / 8), 256>>>(x, W_Q, out_xq);

    // 3) merged final-logit dots (q0 over H, qk over T)
    dots_kernel<<<dim3(PB, PH / 8 + PT / 8), 256>>>(W_hi0);

    // 4) FUSED: gemm + rowblock-pipelined scans + overlapped tail1
    lg_scan_kernel<<<PB + N_GEMM + N_TAIL, 256, FUSED_SMEM>>>(
        pxKh, pxKl, W_hi0, pL0, pG, x, W_reinst0);

    // 5) remaining tails
    tail2_kernel<<<384, 256>>>(W_oh0, W_V, out_reinst);
    proj_kernel<<<dim3(PB, 8), 256>>>(W_proj, out_main);
}

// round 17
// speedup vs baseline: 1.0551x; 1.0551x over previous
#include <cuda_runtime.h>
#include <cstdint>
#include <cmath>

// Problem dims: B=32, S=513 (T=512 ctx + 1 query), D=1024, K=256, V=256, H=2048, O=256
#define PB 32
#define PT 512
#define PD 1024
#define PK 256
#define PV 256
#define PH 2048
#define PO 256

// ---------------- device scratch ----------------
__device__ float g_xKh[(size_t)PB * PT * PK];           // 16 MB tf32-hi
__device__ float g_xKl[(size_t)PB * PT * PK];           // 16 MB tf32-lo
__device__ float g_xQ[PB * PK];
__device__ float g_L0[(size_t)PB * PT * PH];            // 128 MB
__device__ float g_G [(size_t)PB * PT * PT];            // 32 MB (lower triangle valid)
__device__ float g_q0[PB * PH];
__device__ float g_qk[PB * PT];
__device__ float g_wt[PB * PH];
__device__ float g_wv[PB * PT];
__device__ float g_ybar[PB * PD];
__device__ float g_mhn[PB * PV];
__device__ float g_rpart[4 * PB * PD];                  // reinst h-split partials
__device__ unsigned g_done[PB];                         // per-batch gemm-tile counters (74)
__device__ unsigned g_sdone[PB];                        // per-batch scan flags (1)
__device__ unsigned g_t1done[PB];                       // per-batch tail1 counters (20)
__device__ unsigned g_mdone[PB];                        // per-batch mhn counters (8)

// ================= mma.sync tf32 helpers (NOT arch-variant-gated) =================
__device__ __forceinline__ uint32_t smem_u32(const void* p) {
    uint32_t a;
    asm("{ .reg .u64 t; cvta.to.shared.u64 t, %1; cvt.u32.u64 %0, t; }" : "=r"(a) : "l"(p));
    return a;
}
__device__ __forceinline__ uint32_t tf32_hi(uint32_t raw) {
    uint32_t u;
    asm("cvt.rna.tf32.f32 %0, %1;" : "=r"(u) : "f"(__uint_as_float(raw)));
    return u;
}
__device__ __forceinline__ uint32_t tf32_lo(uint32_t raw, uint32_t hi) {
    float d = __uint_as_float(raw) - __uint_as_float(hi);
    uint32_t u;
    asm("cvt.rna.tf32.f32 %0, %1;" : "=r"(u) : "f"(d));
    return u;
}
__device__ __forceinline__ void ldmx4(uint32_t* r, uint32_t addr) {
    asm volatile("ldmatrix.sync.aligned.m8n8.x4.shared.b16 {%0,%1,%2,%3}, [%4];"
                 : "=r"(r[0]), "=r"(r[1]), "=r"(r[2]), "=r"(r[3]) : "r"(addr));
}
__device__ __forceinline__ void ldmx2(uint32_t* r, uint32_t addr) {
    asm volatile("ldmatrix.sync.aligned.m8n8.x2.shared.b16 {%0,%1}, [%2];"
                 : "=r"(r[0]), "=r"(r[1]) : "r"(addr));
}
__device__ __forceinline__ void mma8(float* c, const uint32_t* a, const uint32_t* b) {
    asm volatile(
        "mma.sync.aligned.m16n8k8.row.col.f32.tf32.tf32.f32 "
        "{%0,%1,%2,%3}, {%4,%5,%6,%7}, {%8,%9}, {%0,%1,%2,%3};"
        : "+f"(c[0]), "+f"(c[1]), "+f"(c[2]), "+f"(c[3])
        : "r"(a[0]), "r"(a[1]), "r"(a[2]), "r"(a[3]), "r"(b[0]), "r"(b[1]));
}
__device__ __forceinline__ void cp16(uint32_t dst, const void* src) {
    asm volatile("cp.async.ca.shared.global [%0], [%1], 16;" :: "r"(dst), "l"(src) : "memory");
}
__device__ __forceinline__ void cp_commit() {
    asm volatile("cp.async.commit_group;" ::: "memory");
}
__device__ __forceinline__ void cp_wait6() {
    asm volatile("cp.async.wait_group 6;" ::: "memory");
}
__device__ __forceinline__ void cp_wait1() {
    asm volatile("cp.async.wait_group 1;" ::: "memory");
}
__device__ __forceinline__ void cp_wait0() {
    asm volatile("cp.async.wait_group 0;" ::: "memory");
}

#define TSTRIDE 20                     // floats per smem row (16 data + 4 pad)
#define TILE_F (128 * TSTRIDE)
#define FUSED_SMEM (8 * TILE_F * 4)    // 81920 B (== scan ring 8*(2048+512)*4)
#define N_GEMM (74 * PB)               // 2368
#define N_T1   640                     // 128 ybar + 512 reinst-partial
#define N_T2   384                     // 128 reduce + 256 mhn
#define N_PROJ 256

// ================= GEMM 1: xK projection (128x128 tiles, fp32 in, cvt in-register) =================
__global__ void __launch_bounds__(256) gemm_mma(
    const float* __restrict__ Ag, const float* __restrict__ Bg,
    float* __restrict__ Ch, float* __restrict__ Cl,
    int N, int Kd)
{
    __shared__ __align__(16) float smA[2][TILE_F];
    __shared__ __align__(16) float smB[2][TILE_F];

    const float* A = Ag;
    const float* B = Bg;
    const int m0 = blockIdx.y * 128;
    const int n0 = blockIdx.x * 128;
    const int tid = threadIdx.x, wid = tid >> 5, lane = tid & 31;
    const int wm = (wid & 1) * 64;
    const int wn = (wid >> 1) * 32;

    float acc[4][4][4];
    #pragma unroll
    for (int i = 0; i < 4; i++)
        #pragma unroll
        for (int j = 0; j < 4; j++)
            #pragma unroll
            for (int k = 0; k < 4; k++) acc[i][j][k] = 0.f;

    const int p_row0 = tid >> 2, p_q0 = tid & 3;
    const int p_row1 = (tid + 256) >> 2;

    const uint32_t sa0 = smem_u32(smA[0]);
    const uint32_t sb0 = smem_u32(smB[0]);

    const int a_r = (lane & 7) + ((lane >> 3) & 1) * 8;
    const int a_c = (lane >> 4) * 4;
    const int b_r = (lane & 7);
    const int b_c = ((lane >> 3) & 1) * 4;
    const uint32_t aOff = (uint32_t)(((wm + a_r) * TSTRIDE + a_c) * 4);
    const uint32_t bOff = (uint32_t)(((wn + b_r) * TSTRIDE + b_c) * 4);

    const int nc = Kd >> 4;

    auto issue = [&](int c, int bu) {
        const int k0 = c * 16;
        {
            long am = (long)(m0 + p_row0);
            long ar = am + (am >> 9);          // skip query rows
            cp16(sa0 + (uint32_t)((bu * TILE_F + p_row0 * TSTRIDE + p_q0 * 4) * 4),
                 A + ar * (long)Kd + k0 + p_q0 * 4);
            cp16(sb0 + (uint32_t)((bu * TILE_F + p_row0 * TSTRIDE + p_q0 * 4) * 4),
                 B + (long)(n0 + p_row0) * Kd + k0 + p_q0 * 4);
        }
        {
            long am = (long)(m0 + p_row1);
            long ar = am + (am >> 9);
            cp16(sa0 + (uint32_t)((bu * TILE_F + p_row1 * TSTRIDE + p_q0 * 4) * 4),
                 A + ar * (long)Kd + k0 + p_q0 * 4);
            cp16(sb0 + (uint32_t)((bu * TILE_F + p_row1 * TSTRIDE + p_q0 * 4) * 4),
                 B + (long)(n0 + p_row1) * Kd + k0 + p_q0 * 4);
        }
        cp_commit();
    };

    issue(0, 0);
    for (int c = 0; c < nc; c++) {
        const int bu = c & 1;
        if (c + 1 < nc) { issue(c + 1, bu ^ 1); cp_wait1(); }
        else            { cp_wait0(); }
        __syncthreads();

        const uint32_t aB = sa0 + (uint32_t)(bu * TILE_F * 4) + aOff;
        const uint32_t bB = sb0 + (uint32_t)(bu * TILE_F * 4) + bOff;

        #pragma unroll
        for (int k8 = 0; k8 < 2; k8++) {
            uint32_t ar[4][4], br[4][2];
            #pragma unroll
            for (int mi = 0; mi < 4; mi++)
                ldmx4(ar[mi], aB + (uint32_t)((mi * 16 * TSTRIDE) * 4 + k8 * 32));
            #pragma unroll
            for (int ni = 0; ni < 4; ni++)
                ldmx2(br[ni], bB + (uint32_t)((ni * 8 * TSTRIDE) * 4 + k8 * 32));

            uint32_t ah[4][4], bh[4][2];
            #pragma unroll
            for (int mi = 0; mi < 4; mi++)
                #pragma unroll
                for (int j = 0; j < 4; j++) ah[mi][j] = tf32_hi(ar[mi][j]);
            #pragma unroll
            for (int ni = 0; ni < 4; ni++)
                #pragma unroll
                for (int j = 0; j < 2; j++) bh[ni][j] = tf32_hi(br[ni][j]);

            #pragma unroll
            for (int mi = 0; mi < 4; mi++)
                #pragma unroll
                for (int ni = 0; ni < 4; ni++) mma8(acc[mi][ni], ah[mi], bh[ni]);

            uint32_t bl[4][2];
            #pragma unroll
            for (int ni = 0; ni < 4; ni++)
                #pragma unroll
                for (int j = 0; j < 2; j++) bl[ni][j] = tf32_lo(br[ni][j], bh[ni][j]);
            #pragma unroll
            for (int mi = 0; mi < 4; mi++)
                #pragma unroll
                for (int ni = 0; ni < 4; ni++) mma8(acc[mi][ni], ah[mi], bl[ni]);

            uint32_t al[4][4];
            #pragma unroll
            for (int mi = 0; mi < 4; mi++)
                #pragma unroll
                for (int j = 0; j < 4; j++) al[mi][j] = tf32_lo(ar[mi][j], ah[mi][j]);
            #pragma unroll
            for (int mi = 0; mi < 4; mi++)
                #pragma unroll
                for (int ni = 0; ni < 4; ni++) mma8(acc[mi][ni], al[mi], bh[ni]);
        }
        __syncthreads();
    }

    const int er = lane >> 2, ec = (lane & 3) * 2;
    #pragma unroll
    for (int mi = 0; mi < 4; mi++) {
        long row = m0 + wm + mi * 16 + er;
        #pragma unroll
        for (int ni = 0; ni < 4; ni++) {
            long col = n0 + wn + ni * 8 + ec;
            #pragma unroll
            for (int half = 0; half < 2; half++) {
                long off = (row + half * 8) * (long)N + col;
                float v0 = acc[mi][ni][half * 2 + 0];
                float v1 = acc[mi][ni][half * 2 + 1];
                uint32_t h0 = tf32_hi(__float_as_uint(v0));
                uint32_t h1 = tf32_hi(__float_as_uint(v1));
                *reinterpret_cast<float2*>(Ch + off) =
                    make_float2(__uint_as_float(h0), __uint_as_float(h1));
                *reinterpret_cast<float2*>(Cl + off) =
                    make_float2(__uint_as_float(tf32_lo(__float_as_uint(v0), h0)),
                                __uint_as_float(tf32_lo(__float_as_uint(v1), h1)));
            }
        }
    }
}

// ---------------- xQ = x[b, 512, :] @ W_Q^T ; also resets handshake counters ----------------
__global__ void xq_kernel(const float* __restrict__ x, const float* __restrict__ WQ,
                          float* __restrict__ out_xq)
{
    if (blockIdx.x == 0 && blockIdx.y == 0 && threadIdx.x < PB) {
        g_done[threadIdx.x]   = 0u;
        g_sdone[threadIdx.x]  = 0u;
        g_t1done[threadIdx.x] = 0u;
        g_mdone[threadIdx.x]  = 0u;
    }

    int b = blockIdx.x;
    int w = threadIdx.x >> 5, lane = threadIdx.x & 31;
    int n = blockIdx.y * 8 + w;
    const float* xr = x + ((long)b * 513 + 512) * PD;
    const float* wr = WQ + (long)n * PD;
    float s = 0.f;
    for (int k = lane * 4; k < PD; k += 128) {
        float4 a = *reinterpret_cast<const float4*>(xr + k);
        float4 c = *reinterpret_cast<const float4*>(wr + k);
        s += a.x * c.x + a.y * c.y + a.z * c.z + a.w * c.w;
    }
    #pragma unroll
    for (int o = 16; o; o >>= 1) s += __shfl_down_sync(0xffffffffu, s, o);
    if (!lane) {
        g_xQ[b * PK + n] = s;
        out_xq[b * PK + n] = s;
    }
}

// ---------------- merged dots: q0 and qk ----------------
__global__ void __launch_bounds__(256) dots_kernel(const float* __restrict__ Whi0)
{
    int b = blockIdx.x, y = blockIdx.y;
    int w = threadIdx.x >> 5, lane = threadIdx.x & 31;
    const float* q = g_xQ + b * PK;
    if (y < PH / 8) {
        int r = y * 8 + w;
        const float* row = Whi0 + ((long)b * PH + r) * PK;
        float s = 0.f;
        for (int k = lane * 4; k < PK; k += 128) {
            float4 a = *reinterpret_cast<const float4*>(row + k);
            float4 qq = *reinterpret_cast<const float4*>(q + k);
            s += a.x * qq.x + a.y * qq.y + a.z * qq.z + a.w * qq.w;
        }
        #pragma unroll
        for (int o = 16; o; o >>= 1) s += __shfl_down_sync(0xffffffffu, s, o);
        if (!lane) g_q0[b * PH + r] = s;
    } else {
        int r = (y - PH / 8) * 8 + w;
        const float* rh = g_xKh + ((size_t)b * PT + r) * PK;
        const float* rl = g_xKl + ((size_t)b * PT + r) * PK;
        float s = 0.f;
        for (int k = lane * 4; k < PK; k += 128) {
            float4 ah = *reinterpret_cast<const float4*>(rh + k);
            float4 al = *reinterpret_cast<const float4*>(rl + k);
            float4 qq = *reinterpret_cast<const float4*>(q + k);
            s += (ah.x + al.x) * qq.x + (ah.y + al.y) * qq.y
               + (ah.z + al.z) * qq.z + (ah.w + al.w) * qq.w;
        }
        #pragma unroll
        for (int o = 16; o; o >>= 1) s += __shfl_down_sync(0xffffffffu, s, o);
        if (!lane) g_qk[b * PT + r] = s;
    }
}

// ================= FUSED: gemm + scan + tail1 + tail2 + proj (all per-batch handshakes) =================
// [0,PB): scan (waits g_done[b]==74 -> publishes g_sdone[b])
// [PB, PB+N_GEMM): gemm tiles, batch-major
// next N_T1: tail1 (waits g_sdone -> publishes g_t1done[b]; 20 arrivals/batch)
// next N_T2: tail2 (reduce waits g_t1done==20; mhn waits g_t1done==20 -> publishes g_mdone[b])
// next N_PROJ: proj (waits g_mdone[b]==8)
__global__ void __launch_bounds__(256, 2) lg_scan_kernel(
    const float* __restrict__ xKh, const float* __restrict__ xKl,
    const float* __restrict__ Whi0,
    float* __restrict__ L0g, float* __restrict__ Gg,
    const float* __restrict__ x, const float* __restrict__ W_reinst0,
    const float* __restrict__ W_oh0, const float* __restrict__ W_V,
    const float* __restrict__ W_proj,
    float* __restrict__ out_reinst, float* __restrict__ out_main)
{
    extern __shared__ float sm[];
    const int tid = threadIdx.x;

    if (blockIdx.x < PB) {
        // ======== SCAN ROLE (depth-8 ring, prefetch distance 7) ========
        const int b = blockIdx.x;
        __shared__ unsigned redm[2][8];
        __shared__ unsigned redh[2][8];
        __shared__ float redf[8];

        if (tid == 0) {
            while (atomicAdd(&g_done[b], 0u) < 74u) __nanosleep(128);
            __threadfence();
        }
        __syncthreads();

        const float* L0b = g_L0 + (size_t)b * PT * PH;
        const float* Gb  = g_G  + (size_t)b * PT * PT;
        const uint32_t sB = smem_u32(sm);
        const uint32_t sGo = (uint32_t)(8 * PH * 4);
        float* L0s = sm;             // [8][PH]
        float* Gs  = sm + 8 * PH;    // [8][PT]

        int last[8];
        #pragma unroll
        for (int i = 0; i < 8; i++) last[i] = -1;

        auto issue_row = [&](int r) {
            const int sl = r & 7;
            cp16(sB + (uint32_t)((sl * PH + tid * 4) * 4),         L0b + (size_t)r * PH + tid * 4);
            cp16(sB + (uint32_t)((sl * PH + (tid + 256) * 4) * 4), L0b + (size_t)r * PH + (tid + 256) * 4);
            if (tid < 128)
                cp16(sB + sGo + (uint32_t)((sl * PT + tid * 4) * 4), Gb + (size_t)r * PT + tid * 4);
        };

        #pragma unroll
        for (int r = 0; r < 7; r++) { issue_row(r); cp_commit(); }
        cp_wait6();
        __syncthreads();

        const int lane = tid & 31, w = tid >> 5;

        for (int t = 0; t < PT; t++) {
            const int slot = t & 7;
            const float* gr = Gs + slot * PT;
            const float* lr = L0s + slot * PH;

            unsigned bestm;
            int besth;
            {
                float v = last[0] < 0 ? lr[tid] : gr[last[0]];
                unsigned u = __float_as_uint(v);
                bestm = (u & 0x80000000u) ? ~u : (u | 0x80000000u);
                besth = tid;
            }
            #pragma unroll
            for (int i = 1; i < 8; i++) {
                float v = last[i] < 0 ? lr[i * 256 + tid] : gr[last[i]];
                unsigned u = __float_as_uint(v);
                u = (u & 0x80000000u) ? ~u : (u | 0x80000000u);
                if (u > bestm) { bestm = u; besth = i * 256 + tid; }
            }
            unsigned m1 = __reduce_max_sync(0xffffffffu, bestm);
            unsigned hc = (bestm == m1) ? (unsigned)besth : 0xffffffffu;
            unsigned mh = __reduce_min_sync(0xffffffffu, hc);
            if (lane == 0) { redm[t & 1][w] = m1; redh[t & 1][w] = mh; }

            if (t + 7 < PT) issue_row(t + 7);
            cp_commit();
            cp_wait6();
            __syncthreads();

            unsigned bm = redm[t & 1][0], bh = redh[t & 1][0];
            #pragma unroll
            for (int j = 1; j < 8; j++) {
                unsigned m2 = redm[t & 1][j], h2 = redh[t & 1][j];
                if (m2 > bm || (m2 == bm && h2 < bh)) { bm = m2; bh = h2; }
            }
            if ((int)(bh & 255u) == tid) last[bh >> 8] = t;
        }

        // ---- inline softmax + weight split ----
        g_wv[b * PT + tid]       = 0.f;
        g_wv[b * PT + 256 + tid] = 0.f;

        float l[8];
        float mx = -3.4e38f;
        #pragma unroll
        for (int i = 0; i < 8; i++) {
            int h = i * 256 + tid;
            int t = last[i];
            l[i] = (t < 0) ? g_q0[b * PH + h] : g_qk[b * PT + t];
            mx = fmaxf(mx, l[i]);
        }
        #pragma unroll
        for (int o = 16; o; o >>= 1) mx = fmaxf(mx, __shfl_xor_sync(0xffffffffu, mx, o));
        if (!lane) redf[w] = mx;
        __syncthreads();
        mx = redf[0];
        #pragma unroll
        for (int j = 1; j < 8; j++) mx = fmaxf(mx, redf[j]);

        float s = 0.f;
        #pragma unroll
        for (int i = 0; i < 8; i++) { l[i] = expf(l[i] - mx); s += l[i]; }
        #pragma unroll
        for (int o = 16; o; o >>= 1) s += __shfl_xor_sync(0xffffffffu, s, o);
        __syncthreads();
        if (!lane) redf[w] = s;
        __syncthreads();
        s = 0.f;
        #pragma unroll
        for (int j = 0; j < 8; j++) s += redf[j];

        float inv = 1.f / s;
        #pragma unroll
        for (int i = 0; i < 8; i++) {
            int h = i * 256 + tid;
            float wgt = l[i] * inv;
            if (last[i] < 0) {
                g_wt[b * PH + h] = wgt;
            } else {
                g_wt[b * PH + h] = 0.f;
                g_wv[b * PT + last[i]] = wgt;
            }
        }

        __threadfence();
        __syncthreads();
        if (tid == 0) atomicAdd(&g_sdone[b], 1u);
        return;
    }

    if (blockIdx.x >= PB + N_GEMM + N_T1 + N_T2) {
        // ======== PROJ ROLE ========
        const int i = blockIdx.x - (PB + N_GEMM + N_T1 + N_T2);
        const int b = i >> 3, o0 = (i & 7) * 32;
        const int lane = tid & 31, w = tid >> 5;
        if (tid == 0) {
            while (atomicAdd(&g_mdone[b], 0u) < 8u) __nanosleep(256);
            __threadfence();
        }
        __syncthreads();
        float* mhn_s = sm;
        if (tid < PV) mhn_s[tid] = g_mhn[b * PV + tid];
        __syncthreads();
        for (int pass = 0; pass < 4; pass++) {
            int o = o0 + pass * 8 + w;
            const float* pr = W_proj + (long)o * PV;
            float s = 0.f;
            for (int vv = lane * 4; vv < PV; vv += 128) {
                float4 a = *reinterpret_cast<const float4*>(pr + vv);
                s += a.x * mhn_s[vv] + a.y * mhn_s[vv + 1] + a.z * mhn_s[vv + 2] + a.w * mhn_s[vv + 3];
            }
            #pragma unroll
            for (int oo = 16; oo; oo >>= 1) s += __shfl_down_sync(0xffffffffu, s, oo);
            if (!lane) out_main[b * PO + o] = s;
        }
        return;
    }

    if (blockIdx.x >= PB + N_GEMM + N_T1) {
        // ======== TAIL2 ROLE (reduce | mhn) ========
        const int i = blockIdx.x - (PB + N_GEMM + N_T1);
        if (i < 128) {
            int b = i >> 2;
            if (tid == 0) {
                while (atomicAdd(&g_t1done[b], 0u) < 20u) __nanosleep(256);
                __threadfence();
            }
            __syncthreads();
            int d = (i & 3) * 256 + tid;
            float s = g_ybar[b * PD + d];
            #pragma unroll
            for (int z = 0; z < 4; z++) s += g_rpart[((size_t)z * PB + b) * PD + d];
            out_reinst[b * PD + d] = s;
        } else {
            int k = i - 128;
            int b = k >> 3, v0 = (k & 7) * 32;
            int lane = tid & 31, w = tid >> 5;
            if (tid == 0) {
                while (atomicAdd(&g_t1done[b], 0u) < 20u) __nanosleep(256);
                __threadfence();
            }
            __syncthreads();
            float* wt_s = sm;             // 2048
            float* yb_s = sm + PH;        // 1024
            #pragma unroll
            for (int q = 0; q < 8; q++) wt_s[q * 256 + tid] = g_wt[b * PH + q * 256 + tid];
            #pragma unroll
            for (int q = 0; q < 4; q++) yb_s[q * 256 + tid] = g_ybar[b * PD + q * 256 + tid];
            __syncthreads();

            for (int pass = 0; pass < 4; pass++) {
                int v = v0 + pass * 8 + w;
                const float* row = W_oh0 + ((long)b * PV + v) * PH;
                float s = 0.f;
                #pragma unroll 4
                for (int h = lane * 4; h < PH; h += 128) {
                    float4 a = *reinterpret_cast<const float4*>(row + h);
                    s += a.x * wt_s[h] + a.y * wt_s[h + 1] + a.z * wt_s[h + 2] + a.w * wt_s[h + 3];
                }
                const float* wvr = W_V + (long)v * PD;
                #pragma unroll 4
                for (int d = lane * 4; d < PD; d += 128) {
                    float4 a = *reinterpret_cast<const float4*>(wvr + d);
                    s += a.x * yb_s[d] + a.y * yb_s[d + 1] + a.z * yb_s[d + 2] + a.w * yb_s[d + 3];
                }
                #pragma unroll
                for (int o = 16; o; o >>= 1) s += __shfl_down_sync(0xffffffffu, s, o);
                if (!lane) g_mhn[b * PV + v] = s;
            }
            __threadfence();
            __syncthreads();
            if (tid == 0) atomicAdd(&g_mdone[b], 1u);
        }
        return;
    }

    if (blockIdx.x >= PB + N_GEMM) {
        // ======== TAIL1 ROLE (ybar + reinst partials) ========
        const int i = blockIdx.x - (PB + N_GEMM);
        float* sb = sm;
        int b;
        if (i < 128) {
            b = i >> 2;
            int d0 = (i & 3) * 256;
            if (tid == 0) {
                while (atomicAdd(&g_sdone[b], 0u) == 0u) __nanosleep(256);
                __threadfence();
            }
            __syncthreads();
            sb[tid]       = g_wv[b * PT + tid];
            sb[256 + tid] = g_wv[b * PT + 256 + tid];
            __syncthreads();
            float yb = 0.f;
            const float* xb = x + (size_t)b * 513 * PD + d0 + tid;
            #pragma unroll 16
            for (int t = 0; t < PT; t++) yb += sb[t] * xb[(size_t)t * PD];
            g_ybar[b * PD + d0 + tid] = yb;
        } else {
            int j = i - 128;
            int z = j >> 7, low = j & 127;
            b = low >> 2;
            int d0 = (low & 3) * 256;
            if (tid == 0) {
                while (atomicAdd(&g_sdone[b], 0u) == 0u) __nanosleep(256);
                __threadfence();
            }
            __syncthreads();
            sb[tid]       = g_wt[b * PH + z * 512 + tid];
            sb[256 + tid] = g_wt[b * PH + z * 512 + 256 + tid];
            __syncthreads();
            float acc = 0.f;
            const float* Wb = W_reinst0 + (size_t)b * PH * PD + (size_t)(z * 512) * PD + d0 + tid;
            #pragma unroll 16
            for (int h = 0; h < 512; h++) acc += sb[h] * Wb[(size_t)h * PD];
            g_rpart[((size_t)z * PB + b) * PD + d0 + tid] = acc;
        }
        __threadfence();
        __syncthreads();
        if (tid == 0) atomicAdd(&g_t1done[b], 1u);
        return;
    }

    // ======== GEMM ROLE ========
    const int idx = blockIdx.x - PB;
    const int z = idx / 74;            // batch-major
    const int tile = idx % 74;

    const float* Ah = xKh + (long)z * PT * PK;
    const float* Al = xKl + (long)z * PT * PK;
    const float* Bh;
    const float* Bl = nullptr;
    float* C;
    int m0, n0, N;
    bool bs;
    if (tile < 64) {
        bs = false;
        n0 = (tile & 15) * 128;
        m0 = (tile >> 4) * 128;
        N = PH;
        Bh = Whi0 + (long)z * PH * PK;
        C = L0g + (size_t)z * PT * PH;
    } else {
        int g = tile - 64;
        int by = (g >= 6) ? 3 : (g >= 3) ? 2 : (g >= 1) ? 1 : 0;
        int bx = g - (by * (by + 1)) / 2;
        bs = true;
        m0 = by * 128;
        n0 = bx * 128;
        N = PT;
        Bh = xKh + (long)z * PT * PK;
        Bl = xKl + (long)z * PT * PK;
        C = Gg + (size_t)z * PT * PT;
    }
    const int Kd = PK;

    const int wid = tid >> 5, lane = tid & 31;
    const int wm = (wid & 1) * 64;
    const int wn = (wid >> 1) * 32;

    const uint32_t sbase = smem_u32(sm);
    const uint32_t OAH = 0, OAL = 2 * TILE_F, OBH = 4 * TILE_F, OBL = 6 * TILE_F;

    float acc[4][4][4];
    #pragma unroll
    for (int i = 0; i < 4; i++)
        #pragma unroll
        for (int j = 0; j < 4; j++)
            #pragma unroll
            for (int k = 0; k < 4; k++) acc[i][j][k] = 0.f;

    const int p_row0 = tid >> 2, p_q0 = tid & 3;
    const int p_row1 = (tid + 256) >> 2;

    const int a_r = (lane & 7) + ((lane >> 3) & 1) * 8;
    const int a_c = (lane >> 4) * 4;
    const int b_r = (lane & 7);
    const int b_c = ((lane >> 3) & 1) * 4;
    const uint32_t aOff = (uint32_t)(((wm + a_r) * TSTRIDE + a_c) * 4);
    const uint32_t bOff = (uint32_t)(((wn + b_r) * TSTRIDE + b_c) * 4);

    const int nc = Kd >> 4;

    auto issue = [&](int c, int bu) {
        const int k0 = c * 16;
        #pragma unroll
        for (int h = 0; h < 2; h++) {
            const int pr = h ? p_row1 : p_row0;
            const uint32_t dof = (uint32_t)((bu * TILE_F + pr * TSTRIDE + p_q0 * 4) * 4);
            const long aoff = (long)(m0 + pr) * Kd + k0 + p_q0 * 4;
            const long boff = (long)(n0 + pr) * Kd + k0 + p_q0 * 4;
            cp16(sbase + OAH * 4 + dof, Ah + aoff);
            cp16(sbase + OAL * 4 + dof, Al + aoff);
            cp16(sbase + OBH * 4 + dof, Bh + boff);
            if (bs) cp16(sbase + OBL * 4 + dof, Bl + boff);
        }
        cp_commit();
    };

    issue(0, 0);
    for (int c = 0; c < nc; c++) {
        const int bu = c & 1;
        if (c + 1 < nc) { issue(c + 1, bu ^ 1); cp_wait1(); }
        else            { cp_wait0(); }
        __syncthreads();

        const uint32_t bufo = (uint32_t)(bu * TILE_F * 4);
        const uint32_t aH = sbase + OAH * 4 + bufo + aOff;
        const uint32_t aL = sbase + OAL * 4 + bufo + aOff;
        const uint32_t bH = sbase + OBH * 4 + bufo + bOff;
        const uint32_t bL = sbase + OBL * 4 + bufo + bOff;

        #pragma unroll
        for (int k8 = 0; k8 < 2; k8++) {
            uint32_t ah[4][4], al[4][4], bh[4][2], bl[4][2];
            #pragma unroll
            for (int mi = 0; mi < 4; mi++) {
                const uint32_t o = (uint32_t)((mi * 16 * TSTRIDE) * 4 + k8 * 32);
                ldmx4(ah[mi], aH + o);
                ldmx4(al[mi], aL + o);
            }
            if (bs) {
                #pragma unroll
                for (int ni = 0; ni < 4; ni++) {
                    const uint32_t o = (uint32_t)((ni * 8 * TSTRIDE) * 4 + k8 * 32);
                    ldmx2(bh[ni], bH + o);
                    ldmx2(bl[ni], bL + o);
                }
            } else {
                #pragma unroll
                for (int ni = 0; ni < 4; ni++) {
                    uint32_t br[2];
                    ldmx2(br, bH + (uint32_t)((ni * 8 * TSTRIDE) * 4 + k8 * 32));
                    bh[ni][0] = tf32_hi(br[0]);
                    bh[ni][1] = tf32_hi(br[1]);
                    bl[ni][0] = tf32_lo(br[0], bh[ni][0]);
                    bl[ni][1] = tf32_lo(br[1], bh[ni][1]);
                }
            }

            #pragma unroll
            for (int mi = 0; mi < 4; mi++)
                #pragma unroll
                for (int ni = 0; ni < 4; ni++) mma8(acc[mi][ni], ah[mi], bh[ni]);
            #pragma unroll
            for (int mi = 0; mi < 4; mi++)
                #pragma unroll
                for (int ni = 0; ni < 4; ni++) mma8(acc[mi][ni], ah[mi], bl[ni]);
            #pragma unroll
            for (int mi = 0; mi < 4; mi++)
                #pragma unroll
                for (int ni = 0; ni < 4; ni++) mma8(acc[mi][ni], al[mi], bh[ni]);
        }
        __syncthreads();
    }

    const int er = lane >> 2, ec = (lane & 3) * 2;
    #pragma unroll
    for (int mi = 0; mi < 4; mi++) {
        long row = m0 + wm + mi * 16 + er;
        #pragma unroll
        for (int ni = 0; ni < 4; ni++) {
            long col = n0 + wn + ni * 8 + ec;
            *reinterpret_cast<float2*>(C + row * (long)N + col) =
                make_float2(acc[mi][ni][0], acc[mi][ni][1]);
            *reinterpret_cast<float2*>(C + (row + 8) * (long)N + col) =
                make_float2(acc[mi][ni][2], acc[mi][ni][3]);
        }
    }

    __threadfence();
    __syncthreads();
    if (tid == 0) atomicAdd(&g_done[z], 1u);
}

// ---------------- launch ----------------
extern "C" void kernel_launch(void* const* d_in, const int* in_sizes, int n_in,
                              void* d_out, int out_size)
{
    const float* x         = (const float*)d_in[0];
    const float* W_Q       = (const float*)d_in[1];
    const float* W_K       = (const float*)d_in[2];
    const float* W_V       = (const float*)d_in[3];
    const float* W_proj    = (const float*)d_in[4];
    const float* W_hi0     = (const float*)d_in[5];
    const float* W_oh0     = (const float*)d_in[6];
    const float* W_reinst0 = (const float*)d_in[7];
    float* out = (float*)d_out;

    float *pxKh, *pxKl, *pL0, *pG;
    cudaGetSymbolAddress((void**)&pxKh, g_xKh);
    cudaGetSymbolAddress((void**)&pxKl, g_xKl);
    cudaGetSymbolAddress((void**)&pL0,  g_L0);
    cudaGetSymbolAddress((void**)&pG,   g_G);

    cudaFuncSetAttribute((const void*)lg_scan_kernel,
                         cudaFuncAttributeMaxDynamicSharedMemorySize, FUSED_SMEM);

    // output layout: [out 32x256 | reinst 32x1024 | xQ 32x256]
    float* out_main   = out;
    float* out_reinst = out + PB * PO;
    float* out_xq     = out + PB * PO + PB * PD;

    // 1) xK = ctx @ W_K^T, stored as tf32 hi/lo pair
    gemm_mma<<<dim3(2, 128, 1), 256>>>(x, W_K, pxKh, pxKl, PK, PD);

    // 2) xQ (also resets handshake counters)
    xq_kernel<<<dim3(PB, PK / 8), 256>>>(x, W_Q, out_xq);

    // 3) merged final-logit dots (q0 over H, qk over T)
    dots_kernel<<<dim3(PB, PH / 8 + PT / 8), 256>>>(W_hi0);

    // 4) FUSED: gemm + scans + tail1 + tail2 + proj (per-batch pipelined)
    lg_scan_kernel<<<PB + N_GEMM + N_T1 + N_T2 + N_PROJ, 256, FUSED_SMEM>>>(
        pxKh, pxKl, W_hi0, pL0, pG, x, W_reinst0,
        W_oh0, W_V, W_proj, out_reinst, out_main);
}